// round 13
// baseline (speedup 1.0000x reference)
#include <cuda_runtime.h>
#include <cuda_bf16.h>
#include <stdint.h>

// Problem constants
#define BB 4
#define HH 4
#define BH (BB*HH)          // 16
#define VV 8
#define NN 16384
#define FD 32
#define NC 32768            // 32*32*32
#define NE (VV*NN)          // entries per bh = 131072
#define NE_TOT (BH*NE)      // 2,097,152 total entries
#define KCAP 12             // bucket capacity (Poisson mean 4 -> ~180 spills total)
#define SPILL_CAP 65536
#define CPB 64              // cells per gather block
#define GTHREADS 512        // gather block size (16 warps x 4 cells = 64)

#define TRANS_BLOCKS (BH * (NN / 32))        // 8192
#define SCAT_BLOCKS  (NE_TOT / 2 / 1024)     // 1024

// ---------------------------------------------------------------------------
// Scratch (device globals — zero-initialized at load; self-cleaning per run)
// ---------------------------------------------------------------------------
__device__ float g_featsT [BH * NN * FD];        // 32 MB [bh][n][f]
__device__ uint2 g_entries[BH * NC * KCAP];      // 48 MB {n, bits(lc)}
__device__ int   g_count  [BH * NC];             // 2 MB (zeroed by gather)
__device__ uint4 g_spill  [SPILL_CAP];           // {bh, c, n, bits(lc)}
__device__ int   g_spill_cnt;                    // zeroed by spill

// ---------------------------------------------------------------------------
// 1) prep: fused transpose + scatter via block-role partition.
//    Blocks [0, TRANS_BLOCKS): transpose feats [bh][f][n] -> [bh][n][f].
//    Blocks [TRANS_BLOCKS, +SCAT_BLOCKS): scatter entries into buckets.
//    Independent roles; counters are already zero (self-cleaning invariant).
// block 1024
// ---------------------------------------------------------------------------
__global__ void prep_kernel(const float* __restrict__ feats,
                            const float* __restrict__ lc,
                            const int* __restrict__ fidx) {
    __shared__ float tile[32][33];
    const int bid = blockIdx.x;

    if (bid < TRANS_BLOCKS) {
        // ---- transpose role ----
        const int bh = bid >> 9;              // /512
        const int n0 = (bid & 511) * 32;
        const int tx = threadIdx.x & 31, ty = threadIdx.x >> 5;
        tile[ty][tx] = feats[(bh * FD + ty) * NN + n0 + tx];     // coalesced n
        __syncthreads();
        g_featsT[(bh * NN + n0 + ty) * FD + tx] = tile[tx][ty];  // coalesced f
    } else {
        // ---- scatter role: 2 entries per thread ----
        const int t  = (bid - TRANS_BLOCKS) * 1024 + threadIdx.x;
        const int i0 = t * 2;
        int2   cc = ((const int2*)fidx)[t];
        float2 ll = ((const float2*)lc)[t];
#pragma unroll
        for (int k = 0; k < 2; k++) {
            int i  = i0 + k;
            int bh = i / NE;
            int n  = i & (NN - 1);
            int c  = (k ? cc.y : cc.x) & (NC - 1);
            float l = k ? ll.y : ll.x;
            int bhc = bh * NC + c;
            int pos = atomicAdd(&g_count[bhc], 1);
            if (pos < KCAP) {
                g_entries[(size_t)bhc * KCAP + pos] =
                    make_uint2((unsigned)n, __float_as_uint(l));
            } else {
                int sp = atomicAdd(&g_spill_cnt, 1);
                if (sp < SPILL_CAP)
                    g_spill[sp] = make_uint4((unsigned)bh, (unsigned)c,
                                             (unsigned)n, __float_as_uint(l));
            }
        }
    }
}

// ---------------------------------------------------------------------------
// 2) gather: block = 64 cells; warp = 4 cells; lane = (cell_sub, f_quad).
//    Entry loads batched to registers; feature loads unrolled+predicated in
//    two 6-entry chunks (MLP ~cnt, bounded regs). Zeroes g_count after read.
// grid (NC/CPB, BH), block 512
// ---------------------------------------------------------------------------
__global__ void gather_kernel(float* __restrict__ out) {
    __shared__ uint2 s_ent[CPB * KCAP];     // 6 KB
    __shared__ int   s_cnt[CPB];
    __shared__ float s_tile[FD][CPB + 1];   // ~8.1 KB

    const int bh = blockIdx.y;
    const int c0 = blockIdx.x * CPB;
    const int t  = threadIdx.x;

    // Phase 1: coalesced staging (768 uint2 over 1.5 rounds) + count read/clear
    {
        const uint2* __restrict__ src =
            g_entries + (size_t)(bh * NC + c0) * KCAP;
        s_ent[t] = src[t];
        if (t + GTHREADS < CPB * KCAP) s_ent[t + GTHREADS] = src[t + GTHREADS];
        if (t < CPB) {
            const int gi = bh * NC + c0 + t;
            s_cnt[t] = min(g_count[gi], KCAP);
            g_count[gi] = 0;                  // self-clean for next run
        }
    }
    __syncthreads();

    // Phase 2: warp w -> cells w*4 .. w*4+3
    const int lane = t & 31;
    const int w    = t >> 5;
    const int cs   = lane >> 3;        // cell within warp (0..3)
    const int fq   = lane & 7;         // float4 index (f = fq*4 .. fq*4+3)
    const int cell = w * 4 + cs;

    const int cnt = s_cnt[cell];
    const float4* __restrict__ ft4 =
        (const float4*)g_featsT + (size_t)bh * NN * (FD / 4);
    const uint2* __restrict__ ep = &s_ent[cell * KCAP];

    float4 m4 = make_float4(0.f, 0.f, 0.f, 0.f);
#pragma unroll
    for (int chunk = 0; chunk < 2; chunk++) {
        uint2 e[KCAP / 2];
#pragma unroll
        for (int j = 0; j < KCAP / 2; j++) e[j] = ep[chunk * (KCAP / 2) + j];
#pragma unroll
        for (int j = 0; j < KCAP / 2; j++) {
            const int jj = chunk * (KCAP / 2) + j;
            if (jj < cnt) {
                const float4 fv = ft4[e[j].x * (FD / 4) + fq];   // LDG.128
                const float  l  = __uint_as_float(e[j].y);
                m4.x = fmaxf(m4.x, fv.x * l);
                m4.y = fmaxf(m4.y, fv.y * l);
                m4.z = fmaxf(m4.z, fv.z * l);
                m4.w = fmaxf(m4.w, fv.w * l);
            }
        }
    }

    s_tile[fq * 4 + 0][cell] = m4.x;    // stride 65: conflict-free
    s_tile[fq * 4 + 1][cell] = m4.y;
    s_tile[fq * 4 + 2][cell] = m4.z;
    s_tile[fq * 4 + 3][cell] = m4.w;
    __syncthreads();

    // Phase 3: coalesced output, 4 rounds of 512
#pragma unroll
    for (int r = 0; r < 4; r++) {
        const int idx = t + r * GTHREADS;
        const int f   = idx >> 6;            // /CPB
        const int cl  = idx & (CPB - 1);
        out[((size_t)bh * FD + f) * NC + c0 + cl] = s_tile[f][cl];
    }
}

// ---------------------------------------------------------------------------
// 3) spill: ~180 overflow entries -> atomicMax into out; single block so the
//    counter reset is race-free. warp per entry, lane = f.
// ---------------------------------------------------------------------------
__global__ void spill_kernel(float* __restrict__ out) {
    const int lane = threadIdx.x & 31;
    const int w    = threadIdx.x >> 5;       // 32 warps
    const int cnt  = min(g_spill_cnt, SPILL_CAP);
    for (int s = w; s < cnt; s += 32) {
        uint4 e = g_spill[s];
        const int bh = (int)e.x, c = (int)e.y, n = (int)e.z;
        const float l = __uint_as_float(e.w);
        const float fv = g_featsT[((size_t)bh * NN + n) * FD + lane];
        const float val = fv * l;
        if (val > 0.f)
            atomicMax((int*)out + ((size_t)bh * FD + lane) * NC + c,
                      __float_as_int(val));
    }
    __syncthreads();
    if (threadIdx.x == 0) g_spill_cnt = 0;   // self-clean for next run
}

// ---------------------------------------------------------------------------
// kernel_launch
//   d_in[0] local_coordinate  float32 [B,H,V,N]
//   d_in[1] flattened_index   int32   [B,H,V,N]
//   d_in[2] features          float32 [B,128,N]
//   d_out   float32 [B,128,32,32,32]
// ---------------------------------------------------------------------------
extern "C" void kernel_launch(void* const* d_in, const int* in_sizes, int n_in,
                              void* d_out, int out_size) {
    const float* lc    = (const float*)d_in[0];
    const int*   fidx  = (const int*)d_in[1];
    const float* feats = (const float*)d_in[2];
    float*       out   = (float*)d_out;

    // 1) fused transpose + scatter
    prep_kernel<<<TRANS_BLOCKS + SCAT_BLOCKS, 1024>>>(feats, lc, fidx);

    // 2) gather -> out (writes every cell; zeroes counters)
    {
        dim3 grid(NC / CPB, BH);
        gather_kernel<<<grid, GTHREADS>>>(out);
    }

    // 3) rare spills (resets spill counter)
    spill_kernel<<<1, 1024>>>(out);
}

// round 14
// speedup vs baseline: 1.3175x; 1.3175x over previous
#include <cuda_runtime.h>
#include <cuda_bf16.h>
#include <stdint.h>

// Problem constants
#define BB 4
#define HH 4
#define BH (BB*HH)          // 16
#define VV 8
#define NN 16384
#define FD 32
#define NC 32768            // 32*32*32
#define NE (VV*NN)          // entries per bh = 131072
#define NE_TOT (BH*NE)      // 2,097,152 total entries
#define KCAP 8              // bucket capacity (measured optimum; do not raise)
#define SPILL_CAP 65536
#define CPB 64              // cells per gather block
#define GTHREADS 512        // gather block size (16 warps x 4 cells = 64)

// ---------------------------------------------------------------------------
// Scratch (device globals — zero-initialized at load; no runtime allocation)
// ---------------------------------------------------------------------------
__device__ float g_featsT [BH * NN * FD];        // 32 MB [bh][n][f]
__device__ uint2 g_entries[BH * NC * KCAP];      // 32 MB {n, bits(lc)}
__device__ int   g_count  [BH * NC];             // 2 MB
__device__ uint4 g_spill  [SPILL_CAP];           // {bh, c, n, bits(lc)}
__device__ int   g_spill_cnt;

// ---------------------------------------------------------------------------
// 1) transpose feats [bh][f][n] -> feats_T [bh][n][f]
//    + first 128 blocks also zero the counters (fused zero kernel)
// block (32,32); grid (NN/32, BH)
// ---------------------------------------------------------------------------
__global__ void transpose_kernel(const float* __restrict__ feats) {
    __shared__ float tile[32][33];
    const int bh = blockIdx.y;
    const int n0 = blockIdx.x * 32;
    const int tx = threadIdx.x, ty = threadIdx.y;

    const int bid = blockIdx.y * gridDim.x + blockIdx.x;
    if (bid < 128) {
        const int tt = ty * 32 + tx;                 // 0..1023
        ((int4*)g_count)[bid * 1024 + tt] = make_int4(0, 0, 0, 0);
        if (bid == 0 && tt == 0) g_spill_cnt = 0;
    }

    tile[ty][tx] = feats[(bh * FD + ty) * NN + n0 + tx];    // coalesced in n
    __syncthreads();
    g_featsT[(bh * NN + n0 + ty) * FD + tx] = tile[tx][ty]; // coalesced in f
}

// ---------------------------------------------------------------------------
// 2) scatter into fixed-capacity buckets, 2 entries per thread
// ---------------------------------------------------------------------------
__global__ void scatter_kernel(const float* __restrict__ lc,
                               const int* __restrict__ fidx) {
    int t = blockIdx.x * blockDim.x + threadIdx.x;
    int i0 = t * 2;
    int2   cc = ((const int2*)fidx)[t];
    float2 ll = ((const float2*)lc)[t];
#pragma unroll
    for (int k = 0; k < 2; k++) {
        int i  = i0 + k;
        int bh = i / NE;
        int n  = i & (NN - 1);
        int c  = (k ? cc.y : cc.x) & (NC - 1);
        float l = k ? ll.y : ll.x;
        int bhc = bh * NC + c;
        int pos = atomicAdd(&g_count[bhc], 1);
        if (pos < KCAP) {
            g_entries[(size_t)bhc * KCAP + pos] =
                make_uint2((unsigned)n, __float_as_uint(l));
        } else {
            int sp = atomicAdd(&g_spill_cnt, 1);
            if (sp < SPILL_CAP)
                g_spill[sp] = make_uint4((unsigned)bh, (unsigned)c,
                                         (unsigned)n, __float_as_uint(l));
        }
    }
}

// ---------------------------------------------------------------------------
// 3) gather: block = 64 cells; warp = 4 cells; lane = (cell_sub, f_quad).
//    Inner loop split: (a) all KCAP entry LDS into registers, (b) unrolled
//    predicated LDG.128 batch -> MLP ~= cnt, no serial LDS->LDG chain.
// grid (NC/CPB, BH), block 512
// ---------------------------------------------------------------------------
__global__ void gather_kernel(float* __restrict__ out) {
    __shared__ uint2 s_ent[CPB * KCAP];     // 4 KB
    __shared__ int   s_cnt[CPB];
    __shared__ float s_tile[FD][CPB + 1];   // ~8.1 KB

    const int bh = blockIdx.y;
    const int c0 = blockIdx.x * CPB;
    const int t  = threadIdx.x;

    // Phase 1: one-round coalesced staging (512 uint2 = 4 KB burst)
    s_ent[t] = g_entries[(size_t)(bh * NC + c0) * KCAP + t];
    if (t < CPB)
        s_cnt[t] = min(g_count[bh * NC + c0 + t], KCAP);
    __syncthreads();

    // Phase 2: warp w -> cells w*4 .. w*4+3
    const int lane = t & 31;
    const int w    = t >> 5;
    const int cs   = lane >> 3;        // cell within warp (0..3)
    const int fq   = lane & 7;         // float4 index (f = fq*4 .. fq*4+3)
    const int cell = w * 4 + cs;

    const int cnt = s_cnt[cell];
    const float4* __restrict__ ft4 =
        (const float4*)g_featsT + (size_t)bh * NN * (FD / 4);
    const uint2* __restrict__ ep = &s_ent[cell * KCAP];

    // (a) batch all entry loads from smem (in-bounds; stale slots masked later)
    uint2 e[KCAP];
#pragma unroll
    for (int j = 0; j < KCAP; j++) e[j] = ep[j];

    // (b) unrolled predicated feature loads + max (ptxas front-batches LDGs)
    float4 m4 = make_float4(0.f, 0.f, 0.f, 0.f);
#pragma unroll
    for (int j = 0; j < KCAP; j++) {
        if (j < cnt) {
            const float4 fv = ft4[e[j].x * (FD / 4) + fq];   // LDG.128
            const float  l  = __uint_as_float(e[j].y);
            m4.x = fmaxf(m4.x, fv.x * l);
            m4.y = fmaxf(m4.y, fv.y * l);
            m4.z = fmaxf(m4.z, fv.z * l);
            m4.w = fmaxf(m4.w, fv.w * l);
        }
    }

    s_tile[fq * 4 + 0][cell] = m4.x;    // stride 65: conflict-free
    s_tile[fq * 4 + 1][cell] = m4.y;
    s_tile[fq * 4 + 2][cell] = m4.z;
    s_tile[fq * 4 + 3][cell] = m4.w;
    __syncthreads();

    // Phase 3: coalesced output, 4 rounds of 512
#pragma unroll
    for (int r = 0; r < 4; r++) {
        const int idx = t + r * GTHREADS;
        const int f   = idx >> 6;            // /CPB
        const int cl  = idx & (CPB - 1);
        out[((size_t)bh * FD + f) * NC + c0 + cl] = s_tile[f][cl];
    }
}

// ---------------------------------------------------------------------------
// 4) spill: entry-level parallel. thread = (entry, f-quad): 8 threads per
//    entry, each 1 float4 feats load + 4 predicated spread atomicMax.
//    grid 592 x 256 covers ~18.9K entries fully parallel; stride loop
//    covers the SPILL_CAP worst case.
// ---------------------------------------------------------------------------
__global__ void spill_kernel(float* __restrict__ out) {
    const int tid = blockIdx.x * blockDim.x + threadIdx.x;
    const int fq  = tid & 7;            // float4 quarter (f = fq*4..fq*4+3)
    const int nt  = (gridDim.x * blockDim.x) >> 3;
    const int cnt = min(g_spill_cnt, SPILL_CAP);
    for (int s = tid >> 3; s < cnt; s += nt) {
        const uint4 e = g_spill[s];     // 8 threads share -> broadcast
        const int bh = (int)e.x, c = (int)e.y, n = (int)e.z;
        const float l = __uint_as_float(e.w);
        const float4 fv = ((const float4*)g_featsT)
                              [((size_t)bh * NN + n) * (FD / 4) + fq];
        int* const ob = (int*)out + ((size_t)bh * FD + fq * 4) * NC + c;
        const float v0 = fv.x * l, v1 = fv.y * l, v2 = fv.z * l, v3 = fv.w * l;
        if (v0 > 0.f) atomicMax(ob + 0 * NC, __float_as_int(v0));
        if (v1 > 0.f) atomicMax(ob + 1 * NC, __float_as_int(v1));
        if (v2 > 0.f) atomicMax(ob + 2 * NC, __float_as_int(v2));
        if (v3 > 0.f) atomicMax(ob + 3 * NC, __float_as_int(v3));
    }
}

// ---------------------------------------------------------------------------
// kernel_launch
//   d_in[0] local_coordinate  float32 [B,H,V,N]
//   d_in[1] flattened_index   int32   [B,H,V,N]
//   d_in[2] features          float32 [B,128,N]
//   d_out   float32 [B,128,32,32,32]
// ---------------------------------------------------------------------------
extern "C" void kernel_launch(void* const* d_in, const int* in_sizes, int n_in,
                              void* d_out, int out_size) {
    const float* lc    = (const float*)d_in[0];
    const int*   fidx  = (const int*)d_in[1];
    const float* feats = (const float*)d_in[2];
    float*       out   = (float*)d_out;

    // 1) transpose feats (+ fused counter zeroing)
    {
        dim3 block(32, 32), grid(NN / 32, BH);
        transpose_kernel<<<grid, block>>>(feats);
    }

    // 2) scatter into buckets (2 entries per thread)
    scatter_kernel<<<(NE_TOT / 2) / 256, 256>>>(lc, fidx);

    // 3) gather -> out (writes every cell)
    {
        dim3 grid(NC / CPB, BH);
        gather_kernel<<<grid, GTHREADS>>>(out);
    }

    // 4) spills (entry-level parallel)
    spill_kernel<<<592, 256>>>(out);
}